// round 1
// baseline (speedup 1.0000x reference)
#include <cuda_runtime.h>
#include <cuda_bf16.h>

#define HH   768
#define WW   768
#define HID  256

// scratch for branch outputs
__device__ float g_hx[HH * HID];
__device__ float g_hy[WW * HID];

// ---------------------------------------------------------------------------
// fast sin: degree-9 minimax polynomial after pi range reduction.
// abs error ~3e-6 on reduced range; args here are at most a few hundred.
// ---------------------------------------------------------------------------
__device__ __forceinline__ float fast_sin(float x) {
    const float INV_PI = 0.3183098861837907f;
    const float PI_HI  = 3.14159274101257324f;   // fp32(pi)
    const float PI_LO  = -8.742277657347586e-8f; // pi - fp32(pi)
    float q  = x * INV_PI;
    int   iq = __float2int_rn(q);
    float fq = (float)iq;
    float r  = fmaf(fq, -PI_HI, x);
    r        = fmaf(fq, -PI_LO, r);
    float r2 = r * r;
    float p  = fmaf(r2, 2.7183114939898219e-6f, -1.9839334836096632e-4f);
    p        = fmaf(r2, p, 8.3333293858894632e-3f);
    p        = fmaf(r2, p, -1.6666666641626524e-1f);
    p        = fmaf(r2 * r, p, r);
    return (iq & 1) ? -p : p;
}

__device__ __forceinline__ float fast_sigmoid(float x) {
    return __fdividef(1.0f, 1.0f + __expf(-x));
}

// ---------------------------------------------------------------------------
// Kernel 1: branch networks. One block = 16 rows of one branch.
// h0 = sin(coord*Wb + bb); h1 = sin(h0 @ Wp1^T + bp1);
// h2 = sin(h1 @ Wp2^T + bp2) reshaped (R=2,HID) and summed over R.
// ---------------------------------------------------------------------------
__global__ __launch_bounds__(256)
void branch_kernel(const float* __restrict__ x, const float* __restrict__ y,
                   const float* __restrict__ Wbx, const float* __restrict__ bbx,
                   const float* __restrict__ Wby, const float* __restrict__ bby,
                   const float* __restrict__ Wp1, const float* __restrict__ bp1,
                   const float* __restrict__ Wp2, const float* __restrict__ bp2)
{
    __shared__ float s0[16][HID];
    __shared__ float s1[16][HID];

    const int t  = threadIdx.x;            // hidden index 0..255
    const int br = blockIdx.y;             // 0: x branch, 1: y branch
    const float* coord = br ? y   : x;
    const float* Wb    = br ? Wby : Wbx;
    const float* bb    = br ? bby : bbx;
    float*       outp  = br ? g_hy : g_hx;
    const int r0 = blockIdx.x * 16;

    // stage h0
    {
        float wv = Wb[t];
        float bv = bb[t];
        #pragma unroll
        for (int r = 0; r < 16; r++)
            s0[r][t] = fast_sin(fmaf(coord[r0 + r], wv, bv));
    }
    __syncthreads();

    // h1 = sin(h0 @ Wp1^T + bp1): thread t owns output column t for all 16 rows
    {
        float acc[16];
        float b = bp1[t];
        #pragma unroll
        for (int r = 0; r < 16; r++) acc[r] = b;
        const float4* wrow = (const float4*)(Wp1 + (size_t)t * HID);
        for (int k4 = 0; k4 < HID / 4; k4++) {
            float4 w = wrow[k4];
            #pragma unroll
            for (int r = 0; r < 16; r++) {
                float4 h = *(const float4*)&s0[r][k4 * 4];
                acc[r] = fmaf(w.x, h.x, acc[r]);
                acc[r] = fmaf(w.y, h.y, acc[r]);
                acc[r] = fmaf(w.z, h.z, acc[r]);
                acc[r] = fmaf(w.w, h.w, acc[r]);
            }
        }
        #pragma unroll
        for (int r = 0; r < 16; r++) s1[r][t] = fast_sin(acc[r]);
    }
    __syncthreads();

    // h2 (512 outputs -> thread t owns n=t and n=t+256) then sum over R=2
    {
        float acc0[16], acc1[16];
        float b0 = bp2[t];
        float b1 = bp2[t + HID];
        #pragma unroll
        for (int r = 0; r < 16; r++) { acc0[r] = b0; acc1[r] = b1; }
        const float4* w0row = (const float4*)(Wp2 + (size_t)t * HID);
        const float4* w1row = (const float4*)(Wp2 + (size_t)(t + HID) * HID);
        for (int k4 = 0; k4 < HID / 4; k4++) {
            float4 w0 = w0row[k4];
            float4 w1 = w1row[k4];
            #pragma unroll
            for (int r = 0; r < 16; r++) {
                float4 h = *(const float4*)&s1[r][k4 * 4];
                acc0[r] = fmaf(w0.x, h.x, acc0[r]);
                acc0[r] = fmaf(w0.y, h.y, acc0[r]);
                acc0[r] = fmaf(w0.z, h.z, acc0[r]);
                acc0[r] = fmaf(w0.w, h.w, acc0[r]);
                acc1[r] = fmaf(w1.x, h.x, acc1[r]);
                acc1[r] = fmaf(w1.y, h.y, acc1[r]);
                acc1[r] = fmaf(w1.z, h.z, acc1[r]);
                acc1[r] = fmaf(w1.w, h.w, acc1[r]);
            }
        }
        #pragma unroll
        for (int r = 0; r < 16; r++)
            outp[(size_t)(r0 + r) * HID + t] = fast_sin(acc0[r]) + fast_sin(acc1[r]);
    }
}

// ---------------------------------------------------------------------------
// Kernel 2: fused merge. Block tile = 16 i x 16 j pairs, all 256 N in 4
// chunks of 64. Thread (tx= n-lane 0..7, ty=0..31; iy=ty&3, jy=ty>>2)
// owns 4 i x 2 j x 8 n accumulators.
//   h[i,j,n]  = sin( sum_k Wm1[n,k]*hx[i,k]*hy[j,k] + bm1[n] )
//   out[c,j,i]= sigmoid( sum_n Wm2[c,n]*h[i,j,n] + bm2[c] )
// ---------------------------------------------------------------------------
#define SW_PITCH 65   // 64 n + 1 pad
#define SH_PITCH 17   // 16 + 1 pad
#define SMEM_FLOATS (256*SW_PITCH + 2*256*SH_PITCH + 3*256 + 256)

__global__ __launch_bounds__(256, 1)
void merge_kernel(const float* __restrict__ Wm1, const float* __restrict__ bm1,
                  const float* __restrict__ Wm2, const float* __restrict__ bm2,
                  float* __restrict__ outg)
{
    extern __shared__ float smem[];
    float* s_w   = smem;                       // [k][64] pitch 65
    float* s_hx  = s_w  + 256 * SW_PITCH;      // [k][16] pitch 17
    float* s_hy  = s_hx + 256 * SH_PITCH;      // [k][16] pitch 17
    float* s_wm2 = s_hy + 256 * SH_PITCH;      // [3][256]
    float* s_bm1 = s_wm2 + 3 * 256;            // [256]

    const int tid = threadIdx.x;
    const int tx  = tid & 7;          // n lane
    const int ty  = tid >> 3;         // 0..31
    const int iy  = ty & 3;
    const int jy  = ty >> 2;          // constant within a warp
    const int i0  = blockIdx.x * 16;
    const int j0  = blockIdx.y * 16;

    // stage hx/hy tiles k-major (k = tid)
    {
        const int k = tid;
        #pragma unroll
        for (int il = 0; il < 16; il++)
            s_hx[k * SH_PITCH + il] = g_hx[(size_t)(i0 + il) * HID + k];
        #pragma unroll
        for (int jl = 0; jl < 16; jl++)
            s_hy[k * SH_PITCH + jl] = g_hy[(size_t)(j0 + jl) * HID + k];
        s_bm1[k] = bm1[k];
        for (int idx = tid; idx < 3 * 256; idx += 256) s_wm2[idx] = Wm2[idx];
    }

    float outacc[4][2][3];
    #pragma unroll
    for (int a = 0; a < 4; a++)
        #pragma unroll
        for (int b = 0; b < 2; b++)
            #pragma unroll
            for (int c = 0; c < 3; c++) outacc[a][b][c] = 0.0f;

    for (int nc = 0; nc < 4; nc++) {
        __syncthreads();
        // stage Wm1 chunk transposed: s_w[k][nl] = Wm1[nc*64+nl][k]
        {
            const float* src = Wm1 + (size_t)(nc * 64) * HID + tid;
            #pragma unroll 8
            for (int nl = 0; nl < 64; nl++)
                s_w[tid * SW_PITCH + nl] = src[(size_t)nl * HID];
        }
        __syncthreads();

        float acc[4][2][8];
        #pragma unroll
        for (int a = 0; a < 4; a++)
            #pragma unroll
            for (int b = 0; b < 2; b++)
                #pragma unroll
                for (int m = 0; m < 8; m++) acc[a][b][m] = 0.0f;

        #pragma unroll 4
        for (int k = 0; k < 256; k++) {
            float ax[4], ay[2], wv[8];
            #pragma unroll
            for (int a = 0; a < 4; a++) ax[a] = s_hx[k * SH_PITCH + iy + 4 * a];
            #pragma unroll
            for (int b = 0; b < 2; b++) ay[b] = s_hy[k * SH_PITCH + jy + 8 * b];
            #pragma unroll
            for (int m = 0; m < 8; m++) wv[m] = s_w[k * SW_PITCH + tx + 8 * m];
            float g[4][2];
            #pragma unroll
            for (int a = 0; a < 4; a++)
                #pragma unroll
                for (int b = 0; b < 2; b++) g[a][b] = ax[a] * ay[b];
            #pragma unroll
            for (int m = 0; m < 8; m++)
                #pragma unroll
                for (int a = 0; a < 4; a++)
                    #pragma unroll
                    for (int b = 0; b < 2; b++)
                        acc[a][b][m] = fmaf(wv[m], g[a][b], acc[a][b][m]);
        }

        // epilogue for this N chunk: sin + fold into out accumulators
        #pragma unroll
        for (int m = 0; m < 8; m++) {
            const int n = nc * 64 + tx + 8 * m;
            const float bv = s_bm1[n];
            const float w0 = s_wm2[0 * 256 + n];
            const float w1 = s_wm2[1 * 256 + n];
            const float w2 = s_wm2[2 * 256 + n];
            #pragma unroll
            for (int a = 0; a < 4; a++)
                #pragma unroll
                for (int b = 0; b < 2; b++) {
                    float h = fast_sin(acc[a][b][m] + bv);
                    outacc[a][b][0] = fmaf(w0, h, outacc[a][b][0]);
                    outacc[a][b][1] = fmaf(w1, h, outacc[a][b][1]);
                    outacc[a][b][2] = fmaf(w2, h, outacc[a][b][2]);
                }
        }
    }

    // reduce over the 8-lane n split (tx = lane&7)
    #pragma unroll
    for (int a = 0; a < 4; a++)
        #pragma unroll
        for (int b = 0; b < 2; b++)
            #pragma unroll
            for (int c = 0; c < 3; c++) {
                float v = outacc[a][b][c];
                v += __shfl_xor_sync(0xffffffffu, v, 1);
                v += __shfl_xor_sync(0xffffffffu, v, 2);
                v += __shfl_xor_sync(0xffffffffu, v, 4);
                outacc[a][b][c] = v;
            }

    if (tx == 0) {
        float b2[3];
        #pragma unroll
        for (int c = 0; c < 3; c++) b2[c] = __ldg(&bm2[c]);
        #pragma unroll
        for (int a = 0; a < 4; a++) {
            const int i = i0 + iy + 4 * a;
            #pragma unroll
            for (int b = 0; b < 2; b++) {
                const int j = j0 + jy + 8 * b;
                #pragma unroll
                for (int c = 0; c < 3; c++) {
                    float v = fast_sigmoid(outacc[a][b][c] + b2[c]);
                    outg[(size_t)c * (HH * WW) + (size_t)j * HH + i] = v;
                }
            }
        }
    }
}

// ---------------------------------------------------------------------------
extern "C" void kernel_launch(void* const* d_in, const int* in_sizes, int n_in,
                              void* d_out, int out_size) {
    const float* x   = (const float*)d_in[0];
    const float* y   = (const float*)d_in[1];
    const float* Wbx = (const float*)d_in[2];
    const float* bbx = (const float*)d_in[3];
    const float* Wby = (const float*)d_in[4];
    const float* bby = (const float*)d_in[5];
    const float* Wp1 = (const float*)d_in[6];
    const float* bp1 = (const float*)d_in[7];
    const float* Wp2 = (const float*)d_in[8];
    const float* bp2 = (const float*)d_in[9];
    const float* Wm1 = (const float*)d_in[10];
    const float* bm1 = (const float*)d_in[11];
    const float* Wm2 = (const float*)d_in[12];
    const float* bm2 = (const float*)d_in[13];
    float* out = (float*)d_out;

    const size_t smem_bytes = SMEM_FLOATS * sizeof(float);
    cudaFuncSetAttribute(merge_kernel,
                         cudaFuncAttributeMaxDynamicSharedMemorySize,
                         (int)smem_bytes);

    branch_kernel<<<dim3(HH / 16, 2), 256>>>(x, y, Wbx, bbx, Wby, bby,
                                             Wp1, bp1, Wp2, bp2);
    merge_kernel<<<dim3(HH / 16, WW / 16), 256, smem_bytes>>>(Wm1, bm1, Wm2, bm2, out);
}

// round 4
// speedup vs baseline: 3.5810x; 3.5810x over previous
#include <cuda_runtime.h>
#include <cstdint>

#define HH   768
#define WW   768
#define HID  256
#define NPIX (HH*WW)

// ---------------- scratch ----------------
__device__ float g_hx[HH * HID];
__device__ float g_hy[WW * HID];
__device__ float g_part[2][3 * NPIX];

// ---------------- helpers ----------------
__device__ __forceinline__ uint32_t f2tf32(float x) {
    uint32_t r;
    asm("cvt.rna.tf32.f32 %0, %1;" : "=r"(r) : "f"(x));
    return r;
}

__device__ __forceinline__ float fast_sin(float x) {
    const float INV_PI = 0.3183098861837907f;
    const float PI_HI  = 3.14159274101257324f;
    const float PI_LO  = -8.742277657347586e-8f;
    int   iq = __float2int_rn(x * INV_PI);
    float fq = (float)iq;
    float r  = fmaf(fq, -PI_HI, x);
    r        = fmaf(fq, -PI_LO, r);
    float r2 = r * r;
    float p  = fmaf(r2, 2.7183114939898219e-6f, -1.9839334836096632e-4f);
    p        = fmaf(r2, p, 8.3333293858894632e-3f);
    p        = fmaf(r2, p, -1.6666666641626524e-1f);
    p        = fmaf(r2 * r, p, r);
    return (iq & 1) ? -p : p;
}

#define MMA_TF32(d, a, b) \
    asm volatile("mma.sync.aligned.m16n8k8.row.col.f32.tf32.tf32.f32 " \
        "{%0,%1,%2,%3}, {%4,%5,%6,%7}, {%8,%9}, {%0,%1,%2,%3};" \
        : "+f"((d)[0]), "+f"((d)[1]), "+f"((d)[2]), "+f"((d)[3]) \
        : "r"((a)[0]), "r"((a)[1]), "r"((a)[2]), "r"((a)[3]), \
          "r"((b).x), "r"((b).y))

// ---------------------------------------------------------------------------
// branch networks (unchanged — validated at rel_err 5.8e-7)
// ---------------------------------------------------------------------------
__global__ __launch_bounds__(256)
void branch_kernel(const float* __restrict__ x, const float* __restrict__ y,
                   const float* __restrict__ Wbx, const float* __restrict__ bbx,
                   const float* __restrict__ Wby, const float* __restrict__ bby,
                   const float* __restrict__ Wp1, const float* __restrict__ bp1,
                   const float* __restrict__ Wp2, const float* __restrict__ bp2)
{
    __shared__ float s0[16][HID];
    __shared__ float s1[16][HID];
    const int t  = threadIdx.x;
    const int br = blockIdx.y;
    const float* coord = br ? y   : x;
    const float* Wb    = br ? Wby : Wbx;
    const float* bb    = br ? bby : bbx;
    float*       outp  = br ? g_hy : g_hx;
    const int r0 = blockIdx.x * 16;
    {
        float wv = Wb[t], bv = bb[t];
        #pragma unroll
        for (int r = 0; r < 16; r++) s0[r][t] = fast_sin(fmaf(coord[r0 + r], wv, bv));
    }
    __syncthreads();
    {
        float acc[16]; float b = bp1[t];
        #pragma unroll
        for (int r = 0; r < 16; r++) acc[r] = b;
        const float4* wrow = (const float4*)(Wp1 + (size_t)t * HID);
        for (int k4 = 0; k4 < HID / 4; k4++) {
            float4 w = wrow[k4];
            #pragma unroll
            for (int r = 0; r < 16; r++) {
                float4 h = *(const float4*)&s0[r][k4 * 4];
                acc[r] = fmaf(w.x, h.x, acc[r]); acc[r] = fmaf(w.y, h.y, acc[r]);
                acc[r] = fmaf(w.z, h.z, acc[r]); acc[r] = fmaf(w.w, h.w, acc[r]);
            }
        }
        #pragma unroll
        for (int r = 0; r < 16; r++) s1[r][t] = fast_sin(acc[r]);
    }
    __syncthreads();
    {
        float acc0[16], acc1[16];
        float b0 = bp2[t], b1 = bp2[t + HID];
        #pragma unroll
        for (int r = 0; r < 16; r++) { acc0[r] = b0; acc1[r] = b1; }
        const float4* w0row = (const float4*)(Wp2 + (size_t)t * HID);
        const float4* w1row = (const float4*)(Wp2 + (size_t)(t + HID) * HID);
        for (int k4 = 0; k4 < HID / 4; k4++) {
            float4 w0 = w0row[k4], w1 = w1row[k4];
            #pragma unroll
            for (int r = 0; r < 16; r++) {
                float4 h = *(const float4*)&s1[r][k4 * 4];
                acc0[r] = fmaf(w0.x, h.x, acc0[r]); acc0[r] = fmaf(w0.y, h.y, acc0[r]);
                acc0[r] = fmaf(w0.z, h.z, acc0[r]); acc0[r] = fmaf(w0.w, h.w, acc0[r]);
                acc1[r] = fmaf(w1.x, h.x, acc1[r]); acc1[r] = fmaf(w1.y, h.y, acc1[r]);
                acc1[r] = fmaf(w1.z, h.z, acc1[r]); acc1[r] = fmaf(w1.w, h.w, acc1[r]);
            }
        }
        #pragma unroll
        for (int r = 0; r < 16; r++)
            outp[(size_t)(r0 + r) * HID + t] = fast_sin(acc0[r]) + fast_sin(acc1[r]);
    }
}

// ---------------------------------------------------------------------------
// merge: persistent mma.sync tf32 kernel.
// CTA tile: M=256 pairs (32 i x 8 j) x N=128 (one half) x K=256.
// Each warp owns ONE j (j = j0 + wid) and the FULL N=128: no pixel is
// shared between warps -> single owner per output store.
// B-half staged once per CTA, fragments packed so one LDS.128 covers 2 n-tiles.
// ---------------------------------------------------------------------------
#define SMB_B    0                       // 128n x 256k tf32 frag layout: 131072 B
#define SMB_HX   131072                  // 32 x 260 fp32 = 33280 B
#define SMB_HY   164352                  // 8 x 260 fp32  = 8320 B
#define SMB_BM1  172672                  // 128 fp32
#define SMB_WM2  173184                  // 3 x 128 fp32
#define SMB_TOT  174720

#define HX_PITCH 260
#define N_ITILES 24     // 768/32
#define N_JTILES 96     // 768/8
#define TILES    (N_ITILES * N_JTILES)   // 2304 per half
#define N_GROUPS 74

__global__ __launch_bounds__(256, 1)
void merge_kernel(const float* __restrict__ Wm1, const float* __restrict__ bm1,
                  const float* __restrict__ Wm2)
{
    extern __shared__ __align__(16) char smem[];
    uint32_t* sB   = (uint32_t*)(smem + SMB_B);
    float*    s_hx = (float*)(smem + SMB_HX);
    float*    s_hy = (float*)(smem + SMB_HY);
    float*    s_b1 = (float*)(smem + SMB_BM1);
    float*    s_w2 = (float*)(smem + SMB_WM2);

    const int tid  = threadIdx.x;
    const int wid  = tid >> 5;     // warp = j owner
    const int lane = tid & 31;
    const int qk   = lane & 3;     // k col / n-pair selector
    const int qr   = lane >> 2;    // row selector

    const int cta   = blockIdx.x;
    const int half  = cta & 1;
    const int group = cta >> 1;    // 0..73
    const int h0    = half * 128;

    // ---- one-time: stage B-half in paired fragment layout (tf32) ----
    // element (n,k): ktile=k>>3, ntile=n>>3, lane=(n&7)*4+(k&3), reg=(k>>2)&1
    // pair=ntile>>1, sub=ntile&1
    // u32 index = ((ktile*8+pair)*32 + lane)*4 + sub*2 + reg
    for (int idx = tid; idx < 128 * 64; idx += 256) {
        const int n  = idx >> 6;
        const int k4 = idx & 63;
        float4 v = *(const float4*)(Wm1 + (size_t)(h0 + n) * HID + k4 * 4);
        const int ktile = k4 >> 1;
        const int reg   = k4 & 1;
        const int base  = (((ktile * 8 + (n >> 4)) * 32 + (n & 7) * 4) * 4)
                          + ((n >> 3) & 1) * 2 + reg;
        sB[base +  0] = f2tf32(v.x);
        sB[base +  4] = f2tf32(v.y);
        sB[base +  8] = f2tf32(v.z);
        sB[base + 12] = f2tf32(v.w);
    }
    if (tid < 128) s_b1[tid] = bm1[h0 + tid];
    for (int idx = tid; idx < 384; idx += 256) {
        const int c = idx >> 7, n = idx & 127;
        s_w2[c * 128 + n] = Wm2[c * HID + h0 + n];
    }
    __syncthreads();

    // ---- persistent tile loop ----
    for (int t = group; t < TILES; t += N_GROUPS) {
        const int i0 = (t % N_ITILES) * 32;
        const int j0 = (t / N_ITILES) * 8;

        __syncthreads();
        for (int idx = tid; idx < 32 * 64; idx += 256) {
            const int r = idx >> 6, c4 = idx & 63;
            *(float4*)&s_hx[r * HX_PITCH + c4 * 4] =
                *(const float4*)&g_hx[(size_t)(i0 + r) * HID + c4 * 4];
        }
        for (int idx = tid; idx < 8 * 64; idx += 256) {
            const int r = idx >> 6, c4 = idx & 63;
            *(float4*)&s_hy[r * HX_PITCH + c4 * 4] =
                *(const float4*)&g_hy[(size_t)(j0 + r) * HID + c4 * 4];
        }
        __syncthreads();

        // accumulators initialized with bm1 bias (MMA accumulates on top)
        float d[2][16][4];   // [ih][ntile][frag]
        #pragma unroll
        for (int nt = 0; nt < 16; nt++) {
            const float b0 = s_b1[nt * 8 + qk * 2 + 0];
            const float b1 = s_b1[nt * 8 + qk * 2 + 1];
            #pragma unroll
            for (int ih = 0; ih < 2; ih++) {
                d[ih][nt][0] = b0; d[ih][nt][1] = b1;
                d[ih][nt][2] = b0; d[ih][nt][3] = b1;
            }
        }

        const float* hxr = s_hx + qr * HX_PITCH;
        const float* hyr = s_hy + wid * HX_PITCH;

        #pragma unroll 2
        for (int ks = 0; ks < 32; ks++) {
            const int k0 = ks * 8;
            const float y0 = hyr[k0 + qk];
            const float y1 = hyr[k0 + qk + 4];
            float hxa[4], hxb[4];
            #pragma unroll
            for (int u = 0; u < 4; u++) {
                hxa[u] = hxr[u * 8 * HX_PITCH + k0 + qk];
                hxb[u] = hxr[u * 8 * HX_PITCH + k0 + qk + 4];
            }
            // A fragments: rows 16*ih + {qr, qr+8} -> hxa/hxb[2*ih+{0,1}]
            uint32_t a[2][4];
            #pragma unroll
            for (int ih = 0; ih < 2; ih++) {
                a[ih][0] = f2tf32(hxa[2 * ih + 0] * y0);
                a[ih][1] = f2tf32(hxa[2 * ih + 1] * y0);
                a[ih][2] = f2tf32(hxb[2 * ih + 0] * y1);
                a[ih][3] = f2tf32(hxb[2 * ih + 1] * y1);
            }
            const uint4* bp4 = (const uint4*)sB + (size_t)(ks * 8) * 32 + lane;
            #pragma unroll
            for (int p = 0; p < 8; p++) {
                uint4 B2 = bp4[p * 32];
                uint2 bl = make_uint2(B2.x, B2.y);
                uint2 bh = make_uint2(B2.z, B2.w);
                MMA_TF32(d[0][2 * p],     a[0], bl);
                MMA_TF32(d[1][2 * p],     a[1], bl);
                MMA_TF32(d[0][2 * p + 1], a[0], bh);
                MMA_TF32(d[1][2 * p + 1], a[1], bh);
            }
        }

        // ---- epilogue: sin + Wm2 fold + quad reduce + store (single owner) ----
        const int j = j0 + wid;
        #pragma unroll
        for (int ih = 0; ih < 2; ih++) {
            #pragma unroll
            for (int h = 0; h < 2; h++) {
                const int i = i0 + ih * 16 + qr + 8 * h;
                float p0 = 0.f, p1 = 0.f, p2 = 0.f;
                #pragma unroll
                for (int nt = 0; nt < 16; nt++) {
                    #pragma unroll
                    for (int c = 0; c < 2; c++) {
                        const int nl = nt * 8 + qk * 2 + c;
                        float hv = __sinf(d[ih][nt][2 * h + c]);
                        p0 = fmaf(s_w2[nl],       hv, p0);
                        p1 = fmaf(s_w2[128 + nl], hv, p1);
                        p2 = fmaf(s_w2[256 + nl], hv, p2);
                    }
                }
                p0 += __shfl_xor_sync(0xffffffffu, p0, 1);
                p0 += __shfl_xor_sync(0xffffffffu, p0, 2);
                p1 += __shfl_xor_sync(0xffffffffu, p1, 1);
                p1 += __shfl_xor_sync(0xffffffffu, p1, 2);
                p2 += __shfl_xor_sync(0xffffffffu, p2, 1);
                p2 += __shfl_xor_sync(0xffffffffu, p2, 2);
                if (qk == 0) {
                    float* dst = &g_part[half][(size_t)j * HH + i];
                    dst[0]        = p0;
                    dst[NPIX]     = p1;
                    dst[2 * NPIX] = p2;
                }
            }
        }
    }
}

// ---------------------------------------------------------------------------
__global__ __launch_bounds__(256)
void final_kernel(const float* __restrict__ bm2, float* __restrict__ out)
{
    const int idx = blockIdx.x * 256 + threadIdx.x;
    if (idx < 3 * NPIX) {
        const int c = idx / NPIX;
        float v = g_part[0][idx] + g_part[1][idx] + bm2[c];
        out[idx] = __fdividef(1.0f, 1.0f + __expf(-v));
    }
}

// ---------------------------------------------------------------------------
extern "C" void kernel_launch(void* const* d_in, const int* in_sizes, int n_in,
                              void* d_out, int out_size) {
    const float* x   = (const float*)d_in[0];
    const float* y   = (const float*)d_in[1];
    const float* Wbx = (const float*)d_in[2];
    const float* bbx = (const float*)d_in[3];
    const float* Wby = (const float*)d_in[4];
    const float* bby = (const float*)d_in[5];
    const float* Wp1 = (const float*)d_in[6];
    const float* bp1 = (const float*)d_in[7];
    const float* Wp2 = (const float*)d_in[8];
    const float* bp2 = (const float*)d_in[9];
    const float* Wm1 = (const float*)d_in[10];
    const float* bm1 = (const float*)d_in[11];
    const float* Wm2 = (const float*)d_in[12];
    const float* bm2 = (const float*)d_in[13];
    float* out = (float*)d_out;

    cudaFuncSetAttribute(merge_kernel,
                         cudaFuncAttributeMaxDynamicSharedMemorySize, SMB_TOT);

    branch_kernel<<<dim3(HH / 16, 2), 256>>>(x, y, Wbx, bbx, Wby, bby,
                                             Wp1, bp1, Wp2, bp2);
    merge_kernel<<<148, 256, SMB_TOT>>>(Wm1, bm1, Wm2);
    final_kernel<<<(3 * NPIX + 255) / 256, 256>>>(bm2, out);
}

// round 5
// speedup vs baseline: 5.3892x; 1.5050x over previous
#include <cuda_runtime.h>
#include <cuda_fp16.h>
#include <cstdint>

#define HH   768
#define WW   768
#define HID  256
#define NPIX (HH*WW)

// ---------------- scratch ----------------
__device__ float    g_hx[HH * HID];
__device__ float    g_hy[WW * HID];
__device__ uint32_t g_hxh[HH * HID / 2];   // half2-packed
__device__ uint32_t g_hyh[WW * HID / 2];
__device__ float    g_part[2][3 * NPIX];

// ---------------- helpers ----------------
__device__ __forceinline__ uint32_t pack_h2(float lo, float hi) {
    __half2 h = __floats2half2_rn(lo, hi);
    return *reinterpret_cast<uint32_t*>(&h);
}
__device__ __forceinline__ uint32_t hmul2u(uint32_t a, uint32_t b) {
    uint32_t d;
    asm("mul.f16x2 %0, %1, %2;" : "=r"(d) : "r"(a), "r"(b));
    return d;
}
__device__ __forceinline__ float fast_sin(float x) {
    const float INV_PI = 0.3183098861837907f;
    const float PI_HI  = 3.14159274101257324f;
    const float PI_LO  = -8.742277657347586e-8f;
    int   iq = __float2int_rn(x * INV_PI);
    float fq = (float)iq;
    float r  = fmaf(fq, -PI_HI, x);
    r        = fmaf(fq, -PI_LO, r);
    float r2 = r * r;
    float p  = fmaf(r2, 2.7183114939898219e-6f, -1.9839334836096632e-4f);
    p        = fmaf(r2, p, 8.3333293858894632e-3f);
    p        = fmaf(r2, p, -1.6666666641626524e-1f);
    p        = fmaf(r2 * r, p, r);
    return (iq & 1) ? -p : p;
}

#define MMA_F16(d, a, b0, b1) \
    asm volatile("mma.sync.aligned.m16n8k16.row.col.f32.f16.f16.f32 " \
        "{%0,%1,%2,%3}, {%4,%5,%6,%7}, {%8,%9}, {%0,%1,%2,%3};" \
        : "+f"((d)[0]), "+f"((d)[1]), "+f"((d)[2]), "+f"((d)[3]) \
        : "r"((a)[0]), "r"((a)[1]), "r"((a)[2]), "r"((a)[3]), \
          "r"(b0), "r"(b1))

// ---------------------------------------------------------------------------
// branch networks: 1024 threads/block, k-split partials + smem combine.
// ---------------------------------------------------------------------------
#define BR_SMEM_FLOATS (4096 + 4096 + 16384)   // s0, s1, sp
__global__ __launch_bounds__(1024)
void branch_kernel(const float* __restrict__ x, const float* __restrict__ y,
                   const float* __restrict__ Wbx, const float* __restrict__ bbx,
                   const float* __restrict__ Wby, const float* __restrict__ bby,
                   const float* __restrict__ Wp1, const float* __restrict__ bp1,
                   const float* __restrict__ Wp2, const float* __restrict__ bp2)
{
    extern __shared__ float sm[];
    float* s0 = sm;            // [16][256]
    float* s1 = sm + 4096;     // [16][256]
    float* sp = sm + 8192;     // partials: h1 view [4][16][256], h2 view [2][16][512]

    const int tid = threadIdx.x;
    const int t   = tid & 255;
    const int q   = tid >> 8;           // k-quarter 0..3
    const int br  = blockIdx.y;
    const float* coord = br ? y   : x;
    const float* Wb    = br ? Wby : Wbx;
    const float* bb    = br ? bby : bbx;
    float*       outp  = br ? g_hy : g_hx;
    const int r0 = blockIdx.x * 16;

    if (q == 0) {
        float wv = Wb[t], bv = bb[t];
        #pragma unroll
        for (int r = 0; r < 16; r++)
            s0[r * 256 + t] = fast_sin(fmaf(coord[r0 + r], wv, bv));
    }
    __syncthreads();

    // h1 partial over k in [64q, 64q+64)
    {
        float acc[16];
        #pragma unroll
        for (int r = 0; r < 16; r++) acc[r] = 0.0f;
        const float4* wrow = (const float4*)(Wp1 + (size_t)t * HID + 64 * q);
        #pragma unroll 4
        for (int k4 = 0; k4 < 16; k4++) {
            float4 w = wrow[k4];
            const int base = 64 * q + 4 * k4;
            #pragma unroll
            for (int r = 0; r < 16; r++) {
                float4 h = *(const float4*)&s0[r * 256 + base];
                acc[r] = fmaf(w.x, h.x, acc[r]); acc[r] = fmaf(w.y, h.y, acc[r]);
                acc[r] = fmaf(w.z, h.z, acc[r]); acc[r] = fmaf(w.w, h.w, acc[r]);
            }
        }
        #pragma unroll
        for (int r = 0; r < 16; r++) sp[(q * 16 + r) * 256 + t] = acc[r];
    }
    __syncthreads();
    if (q == 0) {
        float b = bp1[t];
        #pragma unroll
        for (int r = 0; r < 16; r++) {
            float v = b + sp[r * 256 + t] + sp[(16 + r) * 256 + t]
                        + sp[(32 + r) * 256 + t] + sp[(48 + r) * 256 + t];
            s1[r * 256 + t] = fast_sin(v);
        }
    }
    __syncthreads();

    // h2 partial: output n = tid&511 over k in [128kh, 128kh+128)
    {
        const int n  = tid & 511;
        const int kh = tid >> 9;
        float acc[16];
        #pragma unroll
        for (int r = 0; r < 16; r++) acc[r] = 0.0f;
        const float4* wrow = (const float4*)(Wp2 + (size_t)n * HID + 128 * kh);
        #pragma unroll 4
        for (int k4 = 0; k4 < 32; k4++) {
            float4 w = wrow[k4];
            const int base = 128 * kh + 4 * k4;
            #pragma unroll
            for (int r = 0; r < 16; r++) {
                float4 h = *(const float4*)&s1[r * 256 + base];
                acc[r] = fmaf(w.x, h.x, acc[r]); acc[r] = fmaf(w.y, h.y, acc[r]);
                acc[r] = fmaf(w.z, h.z, acc[r]); acc[r] = fmaf(w.w, h.w, acc[r]);
            }
        }
        __syncthreads();   // sp reuse: all h1 reads complete
        #pragma unroll
        for (int r = 0; r < 16; r++) sp[(kh * 16 + r) * 512 + n] = acc[r];
    }
    __syncthreads();
    if (tid < 256) {
        float b0 = bp2[t], b1 = bp2[t + 256];
        #pragma unroll
        for (int r = 0; r < 16; r++) {
            float v0 = b0 + sp[r * 512 + t]       + sp[(16 + r) * 512 + t];
            float v1 = b1 + sp[r * 512 + t + 256] + sp[(16 + r) * 512 + t + 256];
            outp[(size_t)(r0 + r) * HID + t] = fast_sin(v0) + fast_sin(v1);
        }
    }
}

// ---------------------------------------------------------------------------
// pack hx/hy to half2
// ---------------------------------------------------------------------------
__global__ __launch_bounds__(256)
void pack_kernel()
{
    const int half_n = HH * HID / 2;   // 98304
    int id = blockIdx.x * 256 + threadIdx.x;
    if (id < 2 * half_n) {
        const float2* src = (id < half_n) ? (const float2*)g_hx : (const float2*)g_hy;
        uint32_t*     dst = (id < half_n) ? g_hxh : g_hyh;
        int k = (id < half_n) ? id : id - half_n;
        float2 v = src[k];
        dst[k] = pack_h2(v.x, v.y);
    }
}

// ---------------------------------------------------------------------------
// merge: persistent fp16 mma.sync m16n8k16.
// CTA tile M=256 (32i x 8j) x N=128 (half) x K=256. Warp owns one j, full N.
// ---------------------------------------------------------------------------
#define SMB_B    0         // 16384 u32 fp16 fragments = 65536 B
#define SMB_HX   65536     // 32 rows x 132 u32 = 16896 B
#define SMB_HY   82432     // 8 rows x 132 u32 = 4224 B
#define SMB_BM1  86656     // 128 f32
#define SMB_WM2  87168     // 3 x 128 f32
#define SMB_TOT  88704

#define HXP 132            // u32 (half2) pitch: bank = 4*row + qk, conflict-free
#define N_ITILES 24
#define TILES    (N_ITILES * 96)   // 2304 per half
#define N_GROUPS 74

__global__ __launch_bounds__(256, 1)
void merge_kernel(const float* __restrict__ Wm1, const float* __restrict__ bm1,
                  const float* __restrict__ Wm2)
{
    extern __shared__ __align__(16) char smem[];
    uint32_t* sBh   = (uint32_t*)(smem + SMB_B);
    uint32_t* s_hx2 = (uint32_t*)(smem + SMB_HX);
    uint32_t* s_hy2 = (uint32_t*)(smem + SMB_HY);
    float*    s_b1  = (float*)(smem + SMB_BM1);
    float*    s_w2  = (float*)(smem + SMB_WM2);

    const int tid  = threadIdx.x;
    const int wid  = tid >> 5;
    const int lane = tid & 31;
    const int qk   = lane & 3;
    const int qr   = lane >> 2;

    const int cta   = blockIdx.x;
    const int hlf   = cta & 1;
    const int group = cta >> 1;
    const int h0    = hlf * 128;

    // ---- one-time: B-half as fp16 mma fragments ----
    // (n,p): p = k-pair. kt=p>>3, reg=(p&7)>>2, qk_l=p&3, nt=n>>3, qr_l=n&7,
    // pr=nt>>1, sub=nt&1. slot = ((kt*8+pr)*32 + qr_l*4+qk_l)*4 + sub*2 + reg
    for (int idx = tid; idx < 128 * 64; idx += 256) {
        const int n  = idx >> 6;
        const int f4 = idx & 63;
        float4 v = *(const float4*)(Wm1 + (size_t)(h0 + n) * HID + f4 * 4);
        uint32_t h2a = pack_h2(v.x, v.y);   // pair p0 = 2*f4
        uint32_t h2b = pack_h2(v.z, v.w);   // pair p1 = 2*f4+1
        const int nt = n >> 3, qr_l = n & 7, pr = nt >> 1, sub = nt & 1;
        #pragma unroll
        for (int e = 0; e < 2; e++) {
            const int p  = 2 * f4 + e;
            const int kt = p >> 3, w8 = p & 7;
            const int slot = (((kt * 8 + pr) * 32 + qr_l * 4 + (w8 & 3)) * 4)
                             + sub * 2 + (w8 >> 2);
            sBh[slot] = e ? h2b : h2a;
        }
    }
    if (tid < 128) s_b1[tid] = bm1[h0 + tid];
    for (int idx = tid; idx < 384; idx += 256) {
        const int c = idx >> 7, n = idx & 127;
        s_w2[c * 128 + n] = Wm2[c * HID + h0 + n];
    }
    __syncthreads();

    // ---- persistent tile loop ----
    for (int t = group; t < TILES; t += N_GROUPS) {
        const int i0 = (t % N_ITILES) * 32;
        const int j0 = (t / N_ITILES) * 8;

        __syncthreads();
        // stage hx (32 rows x 128 half2) / hy (8 x 128) via uint4
        for (int idx = tid; idx < 1024; idx += 256) {
            const int r = idx >> 5, c = idx & 31;
            *(uint4*)(s_hx2 + r * HXP + c * 4) =
                ((const uint4*)(g_hxh + (size_t)(i0 + r) * 128))[c];
        }
        {
            const int r = tid >> 5, c = tid & 31;
            *(uint4*)(s_hy2 + r * HXP + c * 4) =
                ((const uint4*)(g_hyh + (size_t)(j0 + r) * 128))[c];
        }
        __syncthreads();

        // accumulators initialized with bm1 (MMA accumulates on top)
        float d[2][16][4];
        #pragma unroll
        for (int nt = 0; nt < 16; nt++) {
            const float b0 = s_b1[nt * 8 + qk * 2 + 0];
            const float b1 = s_b1[nt * 8 + qk * 2 + 1];
            #pragma unroll
            for (int ih = 0; ih < 2; ih++) {
                d[ih][nt][0] = b0; d[ih][nt][1] = b1;
                d[ih][nt][2] = b0; d[ih][nt][3] = b1;
            }
        }

        const uint32_t* hxb = s_hx2 + qr * HXP;
        const int jbase = wid * HXP;

        #pragma unroll 2
        for (int kt = 0; kt < 16; kt++) {
            const uint32_t hyl = s_hy2[jbase + 8 * kt + qk];
            const uint32_t hyh = s_hy2[jbase + 8 * kt + qk + 4];
            uint32_t xl[4], xh[4];
            #pragma unroll
            for (int u = 0; u < 4; u++) {
                xl[u] = hxb[u * 8 * HXP + 8 * kt + qk];
                xh[u] = hxb[u * 8 * HXP + 8 * kt + qk + 4];
            }
            uint32_t a[2][4];
            #pragma unroll
            for (int ih = 0; ih < 2; ih++) {
                a[ih][0] = hmul2u(xl[2 * ih + 0], hyl);
                a[ih][1] = hmul2u(xl[2 * ih + 1], hyl);
                a[ih][2] = hmul2u(xh[2 * ih + 0], hyh);
                a[ih][3] = hmul2u(xh[2 * ih + 1], hyh);
            }
            const uint4* bp4 = (const uint4*)sBh + (size_t)(kt * 8) * 32 + lane;
            #pragma unroll
            for (int p = 0; p < 8; p++) {
                uint4 B2 = bp4[p * 32];
                MMA_F16(d[0][2 * p],     a[0], B2.x, B2.y);
                MMA_F16(d[1][2 * p],     a[1], B2.x, B2.y);
                MMA_F16(d[0][2 * p + 1], a[0], B2.z, B2.w);
                MMA_F16(d[1][2 * p + 1], a[1], B2.z, B2.w);
            }
        }

        // ---- epilogue: sin + Wm2 fold + quad reduce + single-owner store ----
        const int j = j0 + wid;
        #pragma unroll
        for (int ih = 0; ih < 2; ih++) {
            #pragma unroll
            for (int h = 0; h < 2; h++) {
                const int i = i0 + ih * 16 + qr + 8 * h;
                float p0 = 0.f, p1 = 0.f, p2 = 0.f;
                #pragma unroll
                for (int nt = 0; nt < 16; nt++) {
                    #pragma unroll
                    for (int c = 0; c < 2; c++) {
                        const int nl = nt * 8 + qk * 2 + c;
                        float hv = __sinf(d[ih][nt][2 * h + c]);
                        p0 = fmaf(s_w2[nl],       hv, p0);
                        p1 = fmaf(s_w2[128 + nl], hv, p1);
                        p2 = fmaf(s_w2[256 + nl], hv, p2);
                    }
                }
                p0 += __shfl_xor_sync(0xffffffffu, p0, 1);
                p0 += __shfl_xor_sync(0xffffffffu, p0, 2);
                p1 += __shfl_xor_sync(0xffffffffu, p1, 1);
                p1 += __shfl_xor_sync(0xffffffffu, p1, 2);
                p2 += __shfl_xor_sync(0xffffffffu, p2, 1);
                p2 += __shfl_xor_sync(0xffffffffu, p2, 2);
                if (qk == 0) {
                    float* dst = &g_part[hlf][(size_t)j * HH + i];
                    dst[0]        = p0;
                    dst[NPIX]     = p1;
                    dst[2 * NPIX] = p2;
                }
            }
        }
    }
}

// ---------------------------------------------------------------------------
__global__ __launch_bounds__(256)
void final_kernel(const float* __restrict__ bm2, float* __restrict__ out)
{
    const int idx = blockIdx.x * 256 + threadIdx.x;
    if (idx < 3 * NPIX) {
        const int c = idx / NPIX;
        float v = g_part[0][idx] + g_part[1][idx] + bm2[c];
        out[idx] = __fdividef(1.0f, 1.0f + __expf(-v));
    }
}

// ---------------------------------------------------------------------------
extern "C" void kernel_launch(void* const* d_in, const int* in_sizes, int n_in,
                              void* d_out, int out_size) {
    const float* x   = (const float*)d_in[0];
    const float* y   = (const float*)d_in[1];
    const float* Wbx = (const float*)d_in[2];
    const float* bbx = (const float*)d_in[3];
    const float* Wby = (const float*)d_in[4];
    const float* bby = (const float*)d_in[5];
    const float* Wp1 = (const float*)d_in[6];
    const float* bp1 = (const float*)d_in[7];
    const float* Wp2 = (const float*)d_in[8];
    const float* bp2 = (const float*)d_in[9];
    const float* Wm1 = (const float*)d_in[10];
    const float* bm1 = (const float*)d_in[11];
    const float* Wm2 = (const float*)d_in[12];
    const float* bm2 = (const float*)d_in[13];
    float* out = (float*)d_out;

    cudaFuncSetAttribute(branch_kernel,
                         cudaFuncAttributeMaxDynamicSharedMemorySize,
                         BR_SMEM_FLOATS * 4);
    cudaFuncSetAttribute(merge_kernel,
                         cudaFuncAttributeMaxDynamicSharedMemorySize, SMB_TOT);

    branch_kernel<<<dim3(HH / 16, 2), 1024, BR_SMEM_FLOATS * 4>>>(
        x, y, Wbx, bbx, Wby, bby, Wp1, bp1, Wp2, bp2);
    pack_kernel<<<768, 256>>>();
    merge_kernel<<<148, 256, SMB_TOT>>>(Wm1, bm1, Wm2);
    final_kernel<<<(3 * NPIX + 255) / 256, 256>>>(bm2, out);
}